// round 10
// baseline (speedup 1.0000x reference)
#include <cuda_runtime.h>
#include <math.h>

// Problem constants (fixed by the reference: B=16, N=4096, Z=128)
#define BB 16
#define NN 4096
#define ZZ 128

#define THREADS 512
#define Q 8                     // preds per thread: 512*8 = 4096 = ALL preds of the batch
#define NCTA 296                // 2 CTAs/SM on 148 SMs: all co-resident -> grid barriers safe
#define GTSMAX 232              // max gt-chunk (<=228 actual, padded)
#define NWARPS (THREADS / 32)   // 16
#define NKEYS (BB * NN)         // 65536

// Sorted pred coordinates (by x), rebuilt every call by the 16 sorter CTAs.
__device__ float    g_spx[BB * NN];
__device__ float    g_spy[BB * NN];
__device__ float    g_spz[BB * NN];
// Encoded row-min keys: zero-init == identity for atomicMax == +inf in min-space.
__device__ unsigned g_rmkey[NKEYS];     // 256KB, L2-resident
__device__ float    g_part2[NCTA];
__device__ int      g_c0 = 0;           // barrier after sort
__device__ int      g_c1 = 0;           // barrier after sweep
__device__ int      g_c2 = 0;           // final ticket

// Monotone-DECREASING float->uint map (min(v) <=> max(key)), identity 0.
__device__ __forceinline__ unsigned enc_min(float v) {
    unsigned b = __float_as_uint(v);
    return (b & 0x80000000u) ? b : (~b & 0x7FFFFFFFu);
}
__device__ __forceinline__ float dec_min(unsigned m) {
    return __uint_as_float((m & 0x80000000u) ? m : (~m & 0x7FFFFFFFu));
}
// Monotone-INCREASING float->uint map (max(v) <=> max(key)).
__device__ __forceinline__ unsigned enc_max(float v) {
    unsigned b = __float_as_uint(v);
    return (b & 0x80000000u) ? ~b : (b | 0x80000000u);
}
__device__ __forceinline__ float dec_max(unsigned m) {
    return __uint_as_float((m & 0x80000000u) ? (m & 0x7FFFFFFFu) : ~m);
}
__device__ __forceinline__ unsigned warp_redux_max(unsigned v) {
    unsigned r;
    asm("redux.sync.max.u32 %0, %1, 0xffffffff;" : "=r"(r) : "r"(v));
    return r;
}
// FFMA with immediate 1.0 multiplier: rt_SMSP=1
__device__ __forceinline__ float fma_i1(float a, float c) {
    float d;
    asm("fma.rn.f32 %0, %1, 0f3F800000, %2;" : "=f"(d) : "f"(a), "f"(c));
    return d;
}

__global__ __launch_bounds__(THREADS, 2)
void chamfer_fused(const float* __restrict__ preds,
                   const float* __restrict__ gts,
                   const float* __restrict__ mu,
                   const float* __restrict__ logvar,
                   float* __restrict__ out)
{
    // Sort keys overlap phase-1 tile storage (sort finishes before staging).
    __shared__ union {
        unsigned long long skeys[NN];               // 32KB (sorter CTAs, phase 0)
        struct {
            float4   sg[GTSMAX];                    // (-2gx,-2gy,-2gz,||g||^2)
            float    sgx[GTSMAX];                   // raw gx for bounds
            float    scap[GTSMAX];                  // col-min upper bound per gt
            unsigned scol[NWARPS * GTSMAX];         // per-warp col-min keys
        } p1;
    } u;
    __shared__ float red[THREADS];
    __shared__ int   slast;

    const int cta = blockIdx.x;
    const int tid = threadIdx.x;
    const int wid = tid >> 5;
    const int lane = tid & 31;
    const bool lane0 = (lane == 0);

    // Balanced (batch, chunk) assignment: batches 0-7 -> 19 CTAs, 8-15 -> 18.
    int batch, idx, C;
    if (cta < 152) { batch = cta / 19;             idx = cta % 19;         C = 19; }
    else           { batch = 8 + (cta - 152) / 18; idx = (cta - 152) % 18; C = 18; }
    const int gA  = 2 * ((idx * (NN / 2)) / C);
    const int cnt = 2 * (((idx + 1) * (NN / 2)) / C) - gA;   // even, <= 228

    // ---- Phase 0: CTAs 0..15 bitonic-sort preds of batch==cta by x ----
    if (cta < BB) {
        const float* __restrict__ sb = preds + cta * 3 * NN;
        for (int i = tid; i < NN; i += THREADS) {
            const unsigned long long k =
                ((unsigned long long)enc_max(sb[i]) << 32) | (unsigned)i;
            u.skeys[i] = k;
        }
        __syncthreads();
        for (int k = 2; k <= NN; k <<= 1) {
            for (int j = k >> 1; j > 0; j >>= 1) {
                for (int t = tid; t < NN; t += THREADS) {
                    const int ixj = t ^ j;
                    if (ixj > t) {
                        const unsigned long long a = u.skeys[t];
                        const unsigned long long b = u.skeys[ixj];
                        const bool up = ((t & k) == 0);
                        if (up ? (a > b) : (a < b)) {
                            u.skeys[t]   = b;
                            u.skeys[ixj] = a;
                        }
                    }
                }
                __syncthreads();
            }
        }
        for (int i = tid; i < NN; i += THREADS) {
            const int s = (int)(u.skeys[i] & 0xFFFFFFFFull);
            g_spx[cta * NN + i] = sb[s];
            g_spy[cta * NN + i] = sb[NN + s];
            g_spz[cta * NN + i] = sb[2 * NN + s];
        }
        __syncthreads();
    }

    // ---- Grid barrier 0: sorted arrays ready everywhere ----
    if (tid == 0) {
        __threadfence();
        atomicAdd(&g_c0, 1);
        while (*(volatile int*)&g_c0 < NCTA) __nanosleep(64);
    }
    __syncthreads();
    __threadfence();

    // ---- Stage gts (sg + raw gx) and per-gt col caps ----
    {
        const float* __restrict__ gb = gts + batch * 3 * NN;
        const float* __restrict__ spx = g_spx + batch * NN;
        const float* __restrict__ spy = g_spy + batch * NN;
        const float* __restrict__ spz = g_spz + batch * NN;
        for (int i = tid; i < cnt; i += THREADS) {
            const int n = gA + i;
            const float x0 = gb[n];
            const float x1 = gb[NN + n];
            const float x2 = gb[2 * NN + n];
            u.p1.sg[i]  = make_float4(-2.0f * x0, -2.0f * x1, -2.0f * x2,
                                      x0 * x0 + x1 * x1 + x2 * x2);
            u.p1.sgx[i] = x0;
            // cap = true distance^2 to some pred near gt's x-rank (upper
            // bound on this gt's col-min; conservative by construction).
            int lo = 0, hi = NN;
            while (lo < hi) {
                const int mid = (lo + hi) >> 1;
                if (spx[mid] < x0) lo = mid + 1; else hi = mid;
            }
            int c0 = lo - 4; if (c0 < 0) c0 = 0;
            int c1 = c0 + 8; if (c1 > NN) { c1 = NN; c0 = NN - 8; }
            float cap = 3.4e38f;
            for (int c = c0; c < c1; c++) {
                const float dx = x0 - spx[c];
                const float dy = x1 - spy[c];
                const float dz = x2 - spz[c];
                cap = fminf(cap, dx * dx + dy * dy + dz * dz);
            }
            u.p1.scap[i] = cap;
        }
    }

    // ---- Load this thread's 8 preds: warp owns 256 CONSECUTIVE sorted preds
    float px[Q], py[Q], pz[Q], rp[Q], mn[Q];
    {
        const int base = batch * NN + wid * 256 + lane;
        float lmin = 3.4e38f, lmax = -3.4e38f;
#pragma unroll
        for (int q = 0; q < Q; q++) {
            const int s = base + q * 32;
            px[q] = g_spx[s];
            py[q] = g_spy[s];
            pz[q] = g_spz[s];
            rp[q] = px[q] * px[q] + py[q] * py[q] + pz[q] * pz[q];
            mn[q] = 3.4e38f;
            lmin = fminf(lmin, px[q]);
            lmax = fmaxf(lmax, px[q]);
        }
        red[tid] = lmin;   // unused slot reuse not needed; compute via redux:
        (void)red;
        // warp interval from actual data (correct regardless of sort quality)
        px[0] = px[0];     // no-op
        // xlo/xhi via encoded redux
        float xlo = dec_min(warp_redux_max(enc_min(lmin)));
        float xhi = dec_max(warp_redux_max(enc_max(lmax)));
        // stash in registers via locals below
        red[tid] = 0.0f;
        __syncthreads();

        // ---- Main sweep with interval pruning ----
        unsigned* __restrict__ sc = u.p1.scol + wid * GTSMAX;
        float wmax = 3.4e38f;
        for (int j = 0; j < cnt; j++) {
            if ((j & 15) == 0) {
                float lm = 0.0f;
#pragma unroll
                for (int q = 0; q < Q; q++)
                    lm = fmaxf(lm, fma_i1(mn[q], rp[q]));   // mn+rp >= 0
                wmax = __uint_as_float(warp_redux_max(__float_as_uint(lm)));
            }
            const float gx = u.p1.sgx[j];
            const float dx = fmaxf(fmaxf(xlo - gx, gx - xhi), 0.0f);
            const float lb = dx * dx;
            if (lb > wmax && lb > u.p1.scap[j]) {
                if (lane0) sc[j] = 0u;     // +inf key; some other warp evaluates j
                continue;
            }
            const float4 g = u.p1.sg[j];
            float ca = 3.4e38f;
#pragma unroll
            for (int q = 0; q < Q; q += 2) {
                const float t0 = fmaf(g.x, px[q],   fmaf(g.y, py[q],   fmaf(g.z, pz[q],   g.w)));
                const float t1 = fmaf(g.x, px[q+1], fmaf(g.y, py[q+1], fmaf(g.z, pz[q+1], g.w)));
                mn[q]   = fminf(mn[q],   t0);
                mn[q+1] = fminf(mn[q+1], t1);
                ca = fminf(ca, fma_i1(t0, rp[q]));
                ca = fminf(ca, fma_i1(t1, rp[q+1]));
            }
            const unsigned k = warp_redux_max(enc_min(ca));
            if (lane0) sc[j] = k;
        }
    }

    // ---- Merge partial row-mins: encoded atomicMax on sorted-index slots ----
    {
        const int base = batch * NN + wid * 256 + lane;
#pragma unroll
        for (int q = 0; q < Q; q++)
            atomicMax(&g_rmkey[base + q * 32], enc_min(mn[q] + rp[q]));
    }
    __syncthreads();

    // ---- Cross-warp col-min reduce (integer max) + sum over CTA's gts ----
    float s = 0.0f;
    for (int i = tid; i < cnt; i += THREADS) {
        unsigned c = u.p1.scol[i];
#pragma unroll
        for (int w = 1; w < NWARPS; w++)
            c = max(c, u.p1.scol[w * GTSMAX + i]);
        s += dec_min(c);
    }
    red[tid] = s;
    __syncthreads();
    for (int off = THREADS / 2; off > 0; off >>= 1) {
        if (tid < off) red[tid] += red[tid + off];
        __syncthreads();
    }
    // red[0] = this CTA's col-min sum (kept in smem across the barrier)

    // ---- Grid barrier 1: all atomicMax row merges complete ----
    if (tid == 0) {
        __threadfence();
        atomicAdd(&g_c1, 1);
        while (*(volatile int*)&g_c1 < NCTA) __nanosleep(64);
    }
    __syncthreads();
    __threadfence();

    // ---- Phase 2: distributed fold of keys + KL, reset keys ----
    float f = 0.0f;
    {
        const int bx = blockIdx.x;
        const int ks = (bx * NKEYS) / NCTA;
        const int ke = ((bx + 1) * NKEYS) / NCTA;
        for (int i = ks + tid; i < ke; i += THREADS) {
            f += dec_min(__ldcg(&g_rmkey[i]));
            g_rmkey[i] = 0u;                   // zero == +inf identity
        }
        const int zs = (bx * (BB * ZZ)) / NCTA;
        const int ze = ((bx + 1) * (BB * ZZ)) / NCTA;
        for (int i = zs + tid; i < ze; i += THREADS) {
            const float mm = mu[i];
            const float lv = logvar[i];
            f += -0.5f * (1.0f + lv - mm * mm - expf(lv));
        }
    }
    if (tid == 0) f += red[0];
    __syncthreads();

    red[tid] = f;
    __syncthreads();
    for (int off = THREADS / 2; off > 0; off >>= 1) {
        if (tid < off) red[tid] += red[tid + off];
        __syncthreads();
    }
    if (tid == 0) {
        slast = 0;
        g_part2[blockIdx.x] = red[0];
        __threadfence();
        if (atomicAdd(&g_c2, 1) == NCTA - 1) slast = 1;
    }
    __syncthreads();

    // ---- Last CTA: final fold + write + ticket resets ----
    if (slast) {
        __threadfence();
        float t = 0.0f;
        for (int i = tid; i < NCTA; i += THREADS) t += __ldcg((float*)&g_part2[i]);
        red[tid] = t;
        __syncthreads();
        for (int off = THREADS / 2; off > 0; off >>= 1) {
            if (tid < off) red[tid] += red[tid + off];
            __syncthreads();
        }
        if (tid == 0) {
            out[0] = red[0];
            g_c0 = 0;
            g_c1 = 0;
            g_c2 = 0;
        }
    }
}

extern "C" void kernel_launch(void* const* d_in, const int* in_sizes, int n_in,
                              void* d_out, int out_size)
{
    const float* preds  = (const float*)d_in[0];   // [16, 3, 4096]
    const float* gts    = (const float*)d_in[1];   // [16, 3, 4096]
    const float* mu     = (const float*)d_in[2];   // [16, 128]
    const float* logvar = (const float*)d_in[3];   // [16, 128]
    float* out = (float*)d_out;

    chamfer_fused<<<NCTA, THREADS>>>(preds, gts, mu, logvar, out);
}

// round 11
// speedup vs baseline: 2.0743x; 2.0743x over previous
#include <cuda_runtime.h>
#include <math.h>

// Problem constants (fixed by the reference: B=16, N=4096, Z=128)
#define BB 16
#define NN 4096
#define ZZ 128

#define THREADS 512
#define Q 8                     // preds per thread: 512*8 = 4096 = ALL preds of the batch
#define NCTA 296                // 2 CTAs/SM on 148 SMs: all co-resident -> grid barrier safe
#define GTSMAX 232              // max gt-chunk (<=228 actual, padded)
#define NWARPS (THREADS / 32)   // 16
#define NKEYS (BB * NN)         // 65536

// Encoded row-min keys: zero-init == identity for atomicMax == +inf in min-space.
__device__ unsigned g_rmkey[NKEYS];     // 256KB, L2-resident
__device__ float    g_part2[NCTA];
__device__ int      g_c1 = 0;
__device__ int      g_c2 = 0;

// Monotone-DECREASING float->uint map (min(v) <=> max(key)), identity 0.
__device__ __forceinline__ unsigned enc_min(float v) {
    unsigned b = __float_as_uint(v);
    return (b & 0x80000000u) ? b : (~b & 0x7FFFFFFFu);
}
__device__ __forceinline__ float dec_min(unsigned m) {
    return __uint_as_float((m & 0x80000000u) ? m : (~m & 0x7FFFFFFFu));
}

// Warp-wide max reduction in ONE instruction.
__device__ __forceinline__ unsigned warp_redux_max(unsigned v) {
    unsigned r;
    asm("redux.sync.max.u32 %0, %1, 0xffffffff;" : "=r"(r) : "r"(v));
    return r;
}

// FFMA with immediate 1.0 multiplier: rt_SMSP=1
__device__ __forceinline__ float fma_i1(float a, float c) {
    float d;
    asm("fma.rn.f32 %0, %1, 0f3F800000, %2;" : "=f"(d) : "f"(a), "f"(c));
    return d;
}

__global__ __launch_bounds__(THREADS, 2)
void chamfer_fused(const float* __restrict__ preds,
                   const float* __restrict__ gts,
                   const float* __restrict__ mu,
                   const float* __restrict__ logvar,
                   float* __restrict__ out)
{
    __shared__ float4   sg[GTSMAX];             // (-2gx, -2gy, -2gz, ||g||^2)
    __shared__ unsigned scol[NWARPS * GTSMAX];  // per-warp col-min KEYS
    __shared__ float    red[THREADS];
    __shared__ int      slast;

    // Balanced (batch, chunk) assignment: batches 0-7 -> 19 CTAs, 8-15 -> 18.
    const int cta = blockIdx.x;
    int batch, idx, C;
    if (cta < 152) { batch = cta / 19;            idx = cta % 19;        C = 19; }
    else           { batch = 8 + (cta - 152) / 18; idx = (cta - 152) % 18; C = 18; }
    const int gA  = 2 * ((idx * (NN / 2)) / C);              // even start
    const int cnt = 2 * (((idx + 1) * (NN / 2)) / C) - gA;   // even, <= 228

    const float* __restrict__ pb = preds + batch * 3 * NN;

    const int tid   = threadIdx.x;
    const int wid   = tid >> 5;
    const bool lane0 = (tid & 31) == 0;

    // Stage this CTA's gt chunk (coalesced per-channel loads, pre-scale by -2)
    {
        const float* __restrict__ gb = gts + batch * 3 * NN;
        for (int i = tid; i < cnt; i += THREADS) {
            const int n = gA + i;
            const float x0 = gb[n];
            const float x1 = gb[NN + n];
            const float x2 = gb[2 * NN + n];
            sg[i] = make_float4(-2.0f * x0, -2.0f * x1, -2.0f * x2,
                                x0 * x0 + x1 * x1 + x2 * x2);
        }
    }

    // This thread's 8 preds in registers
    float px[Q], py[Q], pz[Q], rp[Q], mn[Q];
#pragma unroll
    for (int q = 0; q < Q; q++) {
        const int m = tid + q * THREADS;
        px[q] = pb[m];
        py[q] = pb[NN + m];
        pz[q] = pb[2 * NN + m];
        rp[q] = px[q] * px[q] + py[q] * py[q] + pz[q] * pz[q];
        mn[q] = 3.4e38f;
    }
    __syncthreads();

    // Main sweep, 2 gts per iteration. The warp col-min keys are stored one
    // iteration LATE (software pipeline): the redux.sync latency of pair j
    // overlaps the entire compute of pair j+2 instead of stalling the STS.
    {
        unsigned* __restrict__ sc = scol + wid * GTSMAX;
        unsigned kp0 = 0u, kp1 = 0u;
        for (int j = 0; j < cnt; j += 2) {
            if (lane0 && j > 0) {          // store previous pair's keys
                sc[j - 2] = kp0;
                sc[j - 1] = kp1;
            }
            const float4 g0 = sg[j];
            const float4 g1 = sg[j + 1];
            float ca0 = 3.4e38f, ca1 = 3.4e38f;
#pragma unroll
            for (int q = 0; q < Q; q += 2) {
                float t00 = fmaf(g0.x, px[q],   fmaf(g0.y, py[q],   fmaf(g0.z, pz[q],   g0.w)));
                float t01 = fmaf(g0.x, px[q+1], fmaf(g0.y, py[q+1], fmaf(g0.z, pz[q+1], g0.w)));
                float t10 = fmaf(g1.x, px[q],   fmaf(g1.y, py[q],   fmaf(g1.z, pz[q],   g1.w)));
                float t11 = fmaf(g1.x, px[q+1], fmaf(g1.y, py[q+1], fmaf(g1.z, pz[q+1], g1.w)));
                mn[q]   = fminf(mn[q],   fminf(t00, t10));
                mn[q+1] = fminf(mn[q+1], fminf(t01, t11));
                ca0 = fminf(ca0, fma_i1(t00, rp[q]));
                ca0 = fminf(ca0, fma_i1(t01, rp[q+1]));
                ca1 = fminf(ca1, fma_i1(t10, rp[q]));
                ca1 = fminf(ca1, fma_i1(t11, rp[q+1]));
            }
            kp0 = warp_redux_max(enc_min(ca0));
            kp1 = warp_redux_max(enc_min(ca1));
        }
        if (lane0) {                       // drain the pipeline
            sc[cnt - 2] = kp0;
            sc[cnt - 1] = kp1;
        }
    }

    // Merge partial row-mins across gt-chunks: encoded atomicMax (exact,
    // order-independent). Spread addresses, coalesced lanes.
#pragma unroll
    for (int q = 0; q < Q; q++) {
        const int p = tid + q * THREADS;
        atomicMax(&g_rmkey[batch * NN + p], enc_min(mn[q] + rp[q]));
    }

    __syncthreads();

    // Cross-warp col-min reduce (integer max on keys) + sum over this CTA's gts
    float s = 0.0f;
    for (int i = tid; i < cnt; i += THREADS) {
        unsigned c = scol[i];
#pragma unroll
        for (int w = 1; w < NWARPS; w++)
            c = max(c, scol[w * GTSMAX + i]);
        s += dec_min(c);
    }
    red[tid] = s;
    __syncthreads();
    for (int off = THREADS / 2; off > 0; off >>= 1) {
        if (tid < off) red[tid] += red[tid + off];
        __syncthreads();
    }
    // red[0] holds this CTA's col-min sum; stays in smem across the barrier.

    // ---- Grid barrier: all 296 CTAs are co-resident (2/SM x 148) ----
    if (tid == 0) {
        __threadfence();                       // order atomicMax before ticket
        atomicAdd(&g_c1, 1);
        while (*(volatile int*)&g_c1 < NCTA) __nanosleep(64);
    }
    __syncthreads();
    __threadfence();                           // acquire: keys now stable in L2

    // ---- Phase 2: distributed fold (balanced slices), reset keys ----
    float f = 0.0f;
    {
        const int bx = blockIdx.x;             // recompute slices (no live regs)
        const int ks = (bx * NKEYS) / NCTA;
        const int ke = ((bx + 1) * NKEYS) / NCTA;
        for (int i = ks + tid; i < ke; i += THREADS) {
            f += dec_min(__ldcg(&g_rmkey[i]));
            g_rmkey[i] = 0u;                   // zero == +inf identity
        }
        const int zs = (bx * (BB * ZZ)) / NCTA;
        const int ze = ((bx + 1) * (BB * ZZ)) / NCTA;
        for (int i = zs + tid; i < ze; i += THREADS) {
            const float mm = mu[i];
            const float lv = logvar[i];
            f += -0.5f * (1.0f + lv - mm * mm - expf(lv));
        }
    }
    if (tid == 0) f += red[0];                 // fold own col-min sum (from smem)
    __syncthreads();                           // red[0] consumed before overwrite

    red[tid] = f;
    __syncthreads();
    for (int off = THREADS / 2; off > 0; off >>= 1) {
        if (tid < off) red[tid] += red[tid + off];
        __syncthreads();
    }

    if (tid == 0) {
        slast = 0;
        g_part2[blockIdx.x] = red[0];
        __threadfence();
        if (atomicAdd(&g_c2, 1) == NCTA - 1) slast = 1;
    }
    __syncthreads();

    // ---- Last CTA: final fold + write + ticket reset ----
    if (slast) {
        __threadfence();
        float t = 0.0f;
        for (int i = tid; i < NCTA; i += THREADS) t += __ldcg((float*)&g_part2[i]);
        red[tid] = t;
        __syncthreads();
        for (int off = THREADS / 2; off > 0; off >>= 1) {
            if (tid < off) red[tid] += red[tid + off];
            __syncthreads();
        }
        if (tid == 0) {
            out[0] = red[0];
            g_c1 = 0;          // reset tickets for next graph replay
            g_c2 = 0;
        }
    }
}

extern "C" void kernel_launch(void* const* d_in, const int* in_sizes, int n_in,
                              void* d_out, int out_size)
{
    const float* preds  = (const float*)d_in[0];   // [16, 3, 4096]
    const float* gts    = (const float*)d_in[1];   // [16, 3, 4096]
    const float* mu     = (const float*)d_in[2];   // [16, 128]
    const float* logvar = (const float*)d_in[3];   // [16, 128]
    float* out = (float*)d_out;

    chamfer_fused<<<NCTA, THREADS>>>(preds, gts, mu, logvar, out);
}